// round 15
// baseline (speedup 1.0000x reference)
#include <cuda_runtime.h>

#define NNODE 100
#define H     128
#define MPAD  112
#define LDA   132
#define NBUF  (MPAD*LDA)
#define WCH   8192                 // floats per staged weight chunk buffer
#define SMEM_FLOATS (2*NBUF + 2*WCH)
#define SMEM_BYTES  (SMEM_FLOATS*4)
#define NTHREADS 512

// Fragment-packed tf32 weights: msg1[128] | msg2[128] | upd1[256] | upd2[128] rows.
// Layout per matrix: word[(s*8 + nw*2 + h)*128 + g*16 + t*4 + nt] = W[s*8 + h*4 + t][nw*32 + nt*8 + g]
__device__ float g_wp[640 * H];

__device__ __forceinline__ unsigned f2tf(float f) {
    unsigned u; asm("cvt.rna.tf32.f32 %0, %1;" : "=r"(u) : "f"(f)); return u;
}
__device__ __forceinline__ float tfF(float f) { return __uint_as_float(f2tf(f)); }

__global__ void __launch_bounds__(256) prep_kernel(const float* __restrict__ w_msg1,
                                                   const float* __restrict__ w_msg2,
                                                   const float* __restrict__ w_upd1,
                                                   const float* __restrict__ w_upd2) {
    int i = blockIdx.x * 256 + threadIdx.x;   // 0..81919
    int n = i & 127, r = i >> 7;
    const float* src; int k, base;
    if      (r < 128) { src = w_msg1; k = r;       base = 0; }
    else if (r < 256) { src = w_msg2; k = r - 128; base = 128 * 128; }
    else if (r < 512) { src = w_upd1; k = r - 256; base = 2 * 128 * 128; }
    else              { src = w_upd2; k = r - 512; base = 4 * 128 * 128; }
    float v = src[k * H + n];
    int s = k >> 3, ris = k & 7, h = ris >> 2, t = ris & 3;
    int nw = n >> 5, g = n & 7, nt = (n >> 3) & 3;
    g_wp[base + (s * 8 + nw * 2 + h) * 128 + g * 16 + t * 4 + nt] = tfF(v);
}

__device__ __forceinline__ void mma8(float& d0, float& d1, float& d2, float& d3,
                                     unsigned a0, unsigned a1, unsigned a2, unsigned a3,
                                     unsigned b0, unsigned b1) {
    asm volatile(
        "mma.sync.aligned.m16n8k8.row.col.f32.tf32.tf32.f32 "
        "{%0,%1,%2,%3}, {%4,%5,%6,%7}, {%8,%9}, {%0,%1,%2,%3};"
        : "+f"(d0), "+f"(d1), "+f"(d2), "+f"(d3)
        : "r"(a0), "r"(a1), "r"(a2), "r"(a3), "r"(b0), "r"(b1));
}

__device__ __forceinline__ void cp16(float* dst, const float* src) {
    unsigned d = (unsigned)__cvta_generic_to_shared(dst);
    asm volatile("cp.async.cg.shared.global [%0], [%1], 16;" :: "r"(d), "l"(src));
}
#define CP_COMMIT() asm volatile("cp.async.commit_group;")
#define CP_WAIT0()  asm volatile("cp.async.wait_group 0;")

// Stage one chunk. DUAL: two 4096-word regions (msg1-slab + upd1a-slab). Single: 8192 contiguous.
template<bool DUAL>
__device__ __forceinline__ void stage_chunk(float* sW, const float* __restrict__ g1,
                                            const float* __restrict__ g2, int c, int tid) {
    if (DUAL) {
#pragma unroll
        for (int it = 0; it < 2; ++it) {
            int w4 = (tid + it * NTHREADS) * 4;
            cp16(sW + w4, g1 + c * 4096 + w4);
        }
#pragma unroll
        for (int it = 0; it < 2; ++it) {
            int w4 = (tid + it * NTHREADS) * 4;
            cp16(sW + 4096 + w4, g2 + c * 4096 + w4);
        }
    } else {
#pragma unroll
        for (int it = 0; it < 4; ++it) {
            int w4 = (tid + it * NTHREADS) * 4;
            cp16(sW + w4, g1 + c * 8192 + w4);
        }
    }
}

// One chunk of KT_ k-slabs. sWl = chunk base + nw*256 + g*16 + t*4 (lane-adjusted).
template<int KT_, bool DUAL>
__device__ __forceinline__ void gemm_chunk_p(const float* __restrict__ sA,
                                             const float* __restrict__ sWl,
                                             float accA[2][4][4], float accB[2][4][4],
                                             int g, int t, int mtc) {
#pragma unroll
    for (int kt = 0; kt < KT_; ++kt) {
        unsigned a0[2], a1[2], a2[2], a3[2];
#pragma unroll
        for (int m = 0; m < 2; ++m) if (m < mtc) {
            const float* ap = sA + (m * 16 + g) * LDA + kt * 8 + t;
            a0[m] = __float_as_uint(ap[0]);
            a1[m] = __float_as_uint(ap[8 * LDA]);
            a2[m] = __float_as_uint(ap[4]);
            a3[m] = __float_as_uint(ap[8 * LDA + 4]);
        }
        {
            float4 b0 = *reinterpret_cast<const float4*>(sWl + kt * 1024);
            float4 b1 = *reinterpret_cast<const float4*>(sWl + kt * 1024 + 128);
            const float* b0p = &b0.x; const float* b1p = &b1.x;
#pragma unroll
            for (int m = 0; m < 2; ++m) if (m < mtc)
#pragma unroll
                for (int nt = 0; nt < 4; ++nt)
                    mma8(accA[m][nt][0], accA[m][nt][1], accA[m][nt][2], accA[m][nt][3],
                         a0[m], a1[m], a2[m], a3[m],
                         __float_as_uint(b0p[nt]), __float_as_uint(b1p[nt]));
        }
        if (DUAL) {
            float4 b0 = *reinterpret_cast<const float4*>(sWl + 4096 + kt * 1024);
            float4 b1 = *reinterpret_cast<const float4*>(sWl + 4096 + kt * 1024 + 128);
            const float* b0p = &b0.x; const float* b1p = &b1.x;
#pragma unroll
            for (int m = 0; m < 2; ++m) if (m < mtc)
#pragma unroll
                for (int nt = 0; nt < 4; ++nt)
                    mma8(accB[m][nt][0], accB[m][nt][1], accB[m][nt][2], accB[m][nt][3],
                         a0[m], a1[m], a2[m], a3[m],
                         __float_as_uint(b0p[nt]), __float_as_uint(b1p[nt]));
        }
    }
}

template<int KT_, bool DUAL>
__device__ __forceinline__ void run_gemm_p(const float* sAwarp,
                                           const float* __restrict__ gW1,
                                           const float* __restrict__ gW2,
                                           float* sW0, float* sW1,
                                           float accA[2][4][4], float accB[2][4][4],
                                           int chunks, int tid, int g, int t, int nw, int mtc) {
    __syncthreads();                       // A ready; weight buffers free
    stage_chunk<DUAL>(sW0, gW1, gW2, 0, tid);
    CP_COMMIT();
    for (int c = 0; c < chunks; ++c) {
        CP_WAIT0();
        __syncthreads();
        float* cur = (c & 1) ? sW1 : sW0;
        if (c + 1 < chunks) {
            float* nxt = (c & 1) ? sW0 : sW1;
            stage_chunk<DUAL>(nxt, gW1, gW2, c + 1, tid);
            CP_COMMIT();
        }
        gemm_chunk_p<KT_, DUAL>(sAwarp + c * (KT_ * 8),
                                cur + nw * 256 + g * 16 + t * 4,
                                accA, accB, g, t, mtc);
    }
}

__device__ __forceinline__ float indegf(int row) {
    int r = row / 10, c = row - r * 10;
    return (float)((r > 0) + (r < 9) + (c > 0) + (c < 9));
}

__device__ __forceinline__ void zero_acc(float acc[2][4][4]) {
#pragma unroll
    for (int m = 0; m < 2; ++m)
#pragma unroll
        for (int nt = 0; nt < 4; ++nt)
#pragma unroll
            for (int j = 0; j < 4; ++j) acc[m][nt][j] = 0.f;
}

extern "C" __global__ void __launch_bounds__(NTHREADS, 1)
mpnn_kernel(const float* __restrict__ x,
            const float* __restrict__ w_msg1, const float* __restrict__ b_msg1,
            const float* __restrict__ b_msg2,
            const float* __restrict__ b_upd1,
            const float* __restrict__ b_upd2,
            const float* __restrict__ gamma,  const float* __restrict__ beta,
            float* __restrict__ out) {
    extern __shared__ float sm[];
    float* buf0 = sm;                  // X -> S -> U1
    float* buf1 = sm + NBUF;           // Z -> AGG -> h
    float* sW0  = sm + 2 * NBUF;
    float* sW1  = sW0 + WCH;

    const int tid  = threadIdx.x;
    const int warp = tid >> 5, lane = tid & 31;
    const int g = lane >> 2, t = lane & 3;
    const int mw = warp >> 2, nw = warp & 3;     // 4 M-warps x 4 N-warps
    const int mtc = (mw == 3) ? 1 : 2;
    const int b = blockIdx.x;
    const float* xb = x + (size_t)b * NNODE * H;

    const float* Pmsg1  = g_wp;
    const float* Pmsg2  = g_wp + 128 * 128;
    const float* Pupd1a = g_wp + 2 * 128 * 128;          // rows 0..127
    const float* Pupd1b = g_wp + 2 * 128 * 128 + 16384;  // rows 128..255
    const float* Pupd2  = g_wp + 4 * 128 * 128;

    // ---- load X (tf32-rounded) -> buf0, zero pad rows ----
    for (int i = tid; i < NNODE * H / 4; i += NTHREADS) {
        int row = i >> 5, c4 = (i & 31) << 2;
        float4 v = *reinterpret_cast<const float4*>(xb + row * H + c4);
        float* d = buf0 + row * LDA + c4;
        d[0] = tfF(v.x); d[1] = tfF(v.y); d[2] = tfF(v.z); d[3] = tfF(v.w);
    }
    for (int i = tid; i < (MPAD - NNODE) * H; i += NTHREADS)
        buf0[(NNODE + (i >> 7)) * LDA + (i & 127)] = 0.f;

    float accZ[2][4][4], accXU[2][4][4];
    zero_acc(accZ); zero_acc(accXU);

    // ---- fused pass: Z = X@Wmsg1, XU = X@Wupd1a (A read once) ----
    run_gemm_p<4, true>(buf0 + mw * 32 * LDA, Pmsg1, Pupd1a, sW0, sW1,
                        accZ, accXU, 4, tid, g, t, nw, mtc);
    // epilogue: Z (raw fp32) -> buf1
#pragma unroll
    for (int m = 0; m < 2; ++m) if (m < mtc)
#pragma unroll
        for (int nt = 0; nt < 4; ++nt) {
            int r0 = mw * 32 + m * 16 + g, c0 = nw * 32 + nt * 8 + 2 * t;
            float* p = buf1 + r0 * LDA + c0;
            p[0] = accZ[m][nt][0];       p[1] = accZ[m][nt][1];
            p[8 * LDA] = accZ[m][nt][2]; p[8 * LDA + 1] = accZ[m][nt][3];
        }
    __syncthreads();

    // ---- gather: S[v] = sum_d relu(Z[nbr_d(v)] + c_d) -> buf0 (over X) ----
    {
        int k = tid & 127;
        float wl  = w_msg1[H * H + k];        // (H+1)-th row, unrounded
        float b1v = b_msg1[k];
        float c0v = b1v;
        float c1v = b1v + wl * (1.f / 3.f);
        float c2v = b1v + wl * (2.f / 3.f);
        float c3v = b1v + wl;
        for (int v = (tid >> 7); v < NNODE; v += NTHREADS / 128) {
            int r = v / 10, cc = v - r * 10;
            float s = 0.f;
            if (r < 9)  s += fmaxf(buf1[(v + 10) * LDA + k] + c0v, 0.f);
            if (r > 0)  s += fmaxf(buf1[(v - 10) * LDA + k] + c1v, 0.f);
            if (cc < 9) s += fmaxf(buf1[(v + 1)  * LDA + k] + c2v, 0.f);
            if (cc > 0) s += fmaxf(buf1[(v - 1)  * LDA + k] + c3v, 0.f);
            buf0[v * LDA + k] = tfF(s);
        }
        // pad rows of buf0 already zero from X load
    }

    // ---- GEMM2: AGG = S @ Wmsg2 + indeg*b2 -> buf1 (tf32) ----
    zero_acc(accZ);
    run_gemm_p<8, false>(buf0 + mw * 32 * LDA, Pmsg2, Pmsg2, sW0, sW1,
                         accZ, accZ, 2, tid, g, t, nw, mtc);
#pragma unroll
    for (int m = 0; m < 2; ++m) if (m < mtc)
#pragma unroll
        for (int nt = 0; nt < 4; ++nt) {
            int r0 = mw * 32 + m * 16 + g, c0 = nw * 32 + nt * 8 + 2 * t;
            float id0 = indegf(r0), id1 = indegf(r0 + 8);
            float bb0 = b_msg2[c0], bb1 = b_msg2[c0 + 1];
            float* p = buf1 + r0 * LDA + c0;
            p[0] = tfF(accZ[m][nt][0] + id0 * bb0);
            p[1] = tfF(accZ[m][nt][1] + id0 * bb1);
            p[8 * LDA]     = tfF(accZ[m][nt][2] + id1 * bb0);
            p[8 * LDA + 1] = tfF(accZ[m][nt][3] + id1 * bb1);
        }

    // ---- GEMM3b: accXU += AGG @ Wupd1b; U1 = relu(accXU + bu1) -> buf0 (tf32) ----
    run_gemm_p<8, false>(buf1 + mw * 32 * LDA, Pupd1b, Pupd1b, sW0, sW1,
                         accXU, accXU, 2, tid, g, t, nw, mtc);
#pragma unroll
    for (int m = 0; m < 2; ++m) if (m < mtc)
#pragma unroll
        for (int nt = 0; nt < 4; ++nt) {
            int r0 = mw * 32 + m * 16 + g, c0 = nw * 32 + nt * 8 + 2 * t;
            float bb0 = b_upd1[c0], bb1 = b_upd1[c0 + 1];
            float* p = buf0 + r0 * LDA + c0;
            p[0] = tfF(fmaxf(accXU[m][nt][0] + bb0, 0.f));
            p[1] = tfF(fmaxf(accXU[m][nt][1] + bb1, 0.f));
            p[8 * LDA]     = tfF(fmaxf(accXU[m][nt][2] + bb0, 0.f));
            p[8 * LDA + 1] = tfF(fmaxf(accXU[m][nt][3] + bb1, 0.f));
        }

    // ---- GEMM4: U2 = U1 @ Wupd2 + bu2 -> buf1 (fp32) ----
    zero_acc(accZ);
    run_gemm_p<8, false>(buf0 + mw * 32 * LDA, Pupd2, Pupd2, sW0, sW1,
                         accZ, accZ, 2, tid, g, t, nw, mtc);
#pragma unroll
    for (int m = 0; m < 2; ++m) if (m < mtc)
#pragma unroll
        for (int nt = 0; nt < 4; ++nt) {
            int r0 = mw * 32 + m * 16 + g, c0 = nw * 32 + nt * 8 + 2 * t;
            float bb0 = b_upd2[c0], bb1 = b_upd2[c0 + 1];
            float* p = buf1 + r0 * LDA + c0;
            p[0] = accZ[m][nt][0] + bb0;
            p[1] = accZ[m][nt][1] + bb1;
            p[8 * LDA]     = accZ[m][nt][2] + bb0;
            p[8 * LDA + 1] = accZ[m][nt][3] + bb1;
        }
    __syncthreads();

    // ---- residual (unrounded x) + LayerNorm + store ----
    {
        float* ob = out + (size_t)b * NNODE * H;
        int k4 = lane * 4;
        float g0 = gamma[k4], g1 = gamma[k4 + 1], g2 = gamma[k4 + 2], g3 = gamma[k4 + 3];
        float e0 = beta[k4],  e1 = beta[k4 + 1],  e2 = beta[k4 + 2],  e3 = beta[k4 + 3];
        for (int v = warp; v < NNODE; v += NTHREADS / 32) {
            float4 xv = *reinterpret_cast<const float4*>(xb + v * H + k4);
            const float* hp = buf1 + v * LDA + k4;
            float h0 = hp[0] + xv.x, h1 = hp[1] + xv.y;
            float h2 = hp[2] + xv.z, h3 = hp[3] + xv.w;
            float s = h0 + h1 + h2 + h3;
            float q = h0 * h0 + h1 * h1 + h2 * h2 + h3 * h3;
#pragma unroll
            for (int off = 16; off; off >>= 1) {
                s += __shfl_xor_sync(0xFFFFFFFFu, s, off);
                q += __shfl_xor_sync(0xFFFFFFFFu, q, off);
            }
            float mu  = s * (1.f / 128.f);
            float var = q * (1.f / 128.f) - mu * mu;
            float rs  = rsqrtf(var + 1e-5f);
            float4 o;
            o.x = (h0 - mu) * rs * g0 + e0;
            o.y = (h1 - mu) * rs * g1 + e1;
            o.z = (h2 - mu) * rs * g2 + e2;
            o.w = (h3 - mu) * rs * g3 + e3;
            *reinterpret_cast<float4*>(ob + v * H + k4) = o;
        }
    }
}

extern "C" void kernel_launch(void* const* d_in, const int* in_sizes, int n_in,
                              void* d_out, int out_size) {
    const float* x      = (const float*)d_in[0];
    const float* w_msg1 = (const float*)d_in[4];
    const float* b_msg1 = (const float*)d_in[5];
    const float* w_msg2 = (const float*)d_in[6];
    const float* b_msg2 = (const float*)d_in[7];
    const float* w_upd1 = (const float*)d_in[8];
    const float* b_upd1 = (const float*)d_in[9];
    const float* w_upd2 = (const float*)d_in[10];
    const float* b_upd2 = (const float*)d_in[11];
    const float* gamma  = (const float*)d_in[12];
    const float* beta   = (const float*)d_in[13];
    float* out = (float*)d_out;

    int batches = in_sizes[0] / (NNODE * H);

    prep_kernel<<<320, 256>>>(w_msg1, w_msg2, w_upd1, w_upd2);

    cudaFuncSetAttribute(mpnn_kernel, cudaFuncAttributeMaxDynamicSharedMemorySize, SMEM_BYTES);
    mpnn_kernel<<<batches, NTHREADS, SMEM_BYTES>>>(x, w_msg1, b_msg1, b_msg2,
                                                   b_upd1, b_upd2, gamma, beta, out);
}

// round 16
// speedup vs baseline: 1.0013x; 1.0013x over previous
#include <cuda_runtime.h>

#define NNODE 100
#define H     128
#define MPAD  112
#define LDA   132
#define NBUF  (MPAD*LDA)
#define WCH   8192                 // floats per staged weight chunk buffer
#define SMEM_FLOATS (2*NBUF + 2*WCH)
#define SMEM_BYTES  (SMEM_FLOATS*4)
#define NTHREADS 512

// Fragment-packed tf32 weights: msg1[128] | msg2[128] | upd1[256] | upd2[128] rows.
// Layout per matrix: word[(s*8 + nw*2 + h)*128 + g*16 + t*4 + nt] = W[s*8 + h*4 + t][nw*32 + nt*8 + g]
__device__ float g_wp[640 * H];

__device__ __forceinline__ unsigned f2tf(float f) {
    unsigned u; asm("cvt.rna.tf32.f32 %0, %1;" : "=r"(u) : "f"(f)); return u;
}
__device__ __forceinline__ float tfF(float f) { return __uint_as_float(f2tf(f)); }

__global__ void __launch_bounds__(256) prep_kernel(const float* __restrict__ w_msg1,
                                                   const float* __restrict__ w_msg2,
                                                   const float* __restrict__ w_upd1,
                                                   const float* __restrict__ w_upd2) {
    int i = blockIdx.x * 256 + threadIdx.x;   // 0..81919
    int n = i & 127, r = i >> 7;
    const float* src; int k, base;
    if      (r < 128) { src = w_msg1; k = r;       base = 0; }
    else if (r < 256) { src = w_msg2; k = r - 128; base = 128 * 128; }
    else if (r < 512) { src = w_upd1; k = r - 256; base = 2 * 128 * 128; }
    else              { src = w_upd2; k = r - 512; base = 4 * 128 * 128; }
    float v = src[k * H + n];
    int s = k >> 3, ris = k & 7, h = ris >> 2, t = ris & 3;
    int nw = n >> 5, g = n & 7, nt = (n >> 3) & 3;
    g_wp[base + (s * 8 + nw * 2 + h) * 128 + g * 16 + t * 4 + nt] = tfF(v);
}

__device__ __forceinline__ void mma8(float& d0, float& d1, float& d2, float& d3,
                                     unsigned a0, unsigned a1, unsigned a2, unsigned a3,
                                     unsigned b0, unsigned b1) {
    asm volatile(
        "mma.sync.aligned.m16n8k8.row.col.f32.tf32.tf32.f32 "
        "{%0,%1,%2,%3}, {%4,%5,%6,%7}, {%8,%9}, {%0,%1,%2,%3};"
        : "+f"(d0), "+f"(d1), "+f"(d2), "+f"(d3)
        : "r"(a0), "r"(a1), "r"(a2), "r"(a3), "r"(b0), "r"(b1));
}

__device__ __forceinline__ void cp16(float* dst, const float* src) {
    unsigned d = (unsigned)__cvta_generic_to_shared(dst);
    asm volatile("cp.async.cg.shared.global [%0], [%1], 16;" :: "r"(d), "l"(src));
}
#define CP_COMMIT() asm volatile("cp.async.commit_group;")
#define CP_WAIT0()  asm volatile("cp.async.wait_group 0;")

// Stage one chunk. DUAL: two 4096-word regions (msg1-slab + upd1a-slab). Single: 8192 contiguous.
template<bool DUAL>
__device__ __forceinline__ void stage_chunk(float* sW, const float* __restrict__ g1,
                                            const float* __restrict__ g2, int c, int tid) {
    if (DUAL) {
#pragma unroll
        for (int it = 0; it < 2; ++it) {
            int w4 = (tid + it * NTHREADS) * 4;
            cp16(sW + w4, g1 + c * 4096 + w4);
        }
#pragma unroll
        for (int it = 0; it < 2; ++it) {
            int w4 = (tid + it * NTHREADS) * 4;
            cp16(sW + 4096 + w4, g2 + c * 4096 + w4);
        }
    } else {
#pragma unroll
        for (int it = 0; it < 4; ++it) {
            int w4 = (tid + it * NTHREADS) * 4;
            cp16(sW + w4, g1 + c * 8192 + w4);
        }
    }
}

// One chunk of KT_ k-slabs. sWl = chunk base + nw*256 + g*16 + t*4 (lane-adjusted).
template<int KT_, bool DUAL>
__device__ __forceinline__ void gemm_chunk_p(const float* __restrict__ sA,
                                             const float* __restrict__ sWl,
                                             float accA[2][4][4], float accB[2][4][4],
                                             int g, int t, int mtc) {
#pragma unroll
    for (int kt = 0; kt < KT_; ++kt) {
        unsigned a0[2], a1[2], a2[2], a3[2];
#pragma unroll
        for (int m = 0; m < 2; ++m) if (m < mtc) {
            const float* ap = sA + (m * 16 + g) * LDA + kt * 8 + t;
            a0[m] = __float_as_uint(ap[0]);
            a1[m] = __float_as_uint(ap[8 * LDA]);
            a2[m] = __float_as_uint(ap[4]);
            a3[m] = __float_as_uint(ap[8 * LDA + 4]);
        }
        {
            float4 b0 = *reinterpret_cast<const float4*>(sWl + kt * 1024);
            float4 b1 = *reinterpret_cast<const float4*>(sWl + kt * 1024 + 128);
            const float* b0p = &b0.x; const float* b1p = &b1.x;
#pragma unroll
            for (int m = 0; m < 2; ++m) if (m < mtc)
#pragma unroll
                for (int nt = 0; nt < 4; ++nt)
                    mma8(accA[m][nt][0], accA[m][nt][1], accA[m][nt][2], accA[m][nt][3],
                         a0[m], a1[m], a2[m], a3[m],
                         __float_as_uint(b0p[nt]), __float_as_uint(b1p[nt]));
        }
        if (DUAL) {
            float4 b0 = *reinterpret_cast<const float4*>(sWl + 4096 + kt * 1024);
            float4 b1 = *reinterpret_cast<const float4*>(sWl + 4096 + kt * 1024 + 128);
            const float* b0p = &b0.x; const float* b1p = &b1.x;
#pragma unroll
            for (int m = 0; m < 2; ++m) if (m < mtc)
#pragma unroll
                for (int nt = 0; nt < 4; ++nt)
                    mma8(accB[m][nt][0], accB[m][nt][1], accB[m][nt][2], accB[m][nt][3],
                         a0[m], a1[m], a2[m], a3[m],
                         __float_as_uint(b0p[nt]), __float_as_uint(b1p[nt]));
        }
    }
}

template<int KT_, bool DUAL>
__device__ __forceinline__ void run_gemm_p(const float* sAwarp,
                                           const float* __restrict__ gW1,
                                           const float* __restrict__ gW2,
                                           float* sW0, float* sW1,
                                           float accA[2][4][4], float accB[2][4][4],
                                           int chunks, int tid, int g, int t, int nw, int mtc) {
    __syncthreads();                       // A ready; weight buffers free
    stage_chunk<DUAL>(sW0, gW1, gW2, 0, tid);
    CP_COMMIT();
    for (int c = 0; c < chunks; ++c) {
        CP_WAIT0();
        __syncthreads();
        float* cur = (c & 1) ? sW1 : sW0;
        if (c + 1 < chunks) {
            float* nxt = (c & 1) ? sW0 : sW1;
            stage_chunk<DUAL>(nxt, gW1, gW2, c + 1, tid);
            CP_COMMIT();
        }
        gemm_chunk_p<KT_, DUAL>(sAwarp + c * (KT_ * 8),
                                cur + nw * 256 + g * 16 + t * 4,
                                accA, accB, g, t, mtc);
    }
}

__device__ __forceinline__ float indegf(int row) {
    int r = row / 10, c = row - r * 10;
    return (float)((r > 0) + (r < 9) + (c > 0) + (c < 9));
}

__device__ __forceinline__ void zero_acc(float acc[2][4][4]) {
#pragma unroll
    for (int m = 0; m < 2; ++m)
#pragma unroll
        for (int nt = 0; nt < 4; ++nt)
#pragma unroll
            for (int j = 0; j < 4; ++j) acc[m][nt][j] = 0.f;
}

extern "C" __global__ void __launch_bounds__(NTHREADS, 1)
mpnn_kernel(const float* __restrict__ x,
            const float* __restrict__ w_msg1, const float* __restrict__ b_msg1,
            const float* __restrict__ b_msg2,
            const float* __restrict__ b_upd1,
            const float* __restrict__ b_upd2,
            const float* __restrict__ gamma,  const float* __restrict__ beta,
            float* __restrict__ out) {
    extern __shared__ float sm[];
    float* buf0 = sm;                  // X -> S -> U1
    float* buf1 = sm + NBUF;           // Z -> AGG -> h
    float* sW0  = sm + 2 * NBUF;
    float* sW1  = sW0 + WCH;

    const int tid  = threadIdx.x;
    const int warp = tid >> 5, lane = tid & 31;
    const int g = lane >> 2, t = lane & 3;
    const int mw = warp >> 2, nw = warp & 3;     // 4 M-warps x 4 N-warps
    const int mtc = (mw == 3) ? 1 : 2;
    const int b = blockIdx.x;
    const float* xb = x + (size_t)b * NNODE * H;

    const float* Pmsg1  = g_wp;
    const float* Pmsg2  = g_wp + 128 * 128;
    const float* Pupd1a = g_wp + 2 * 128 * 128;          // rows 0..127
    const float* Pupd1b = g_wp + 2 * 128 * 128 + 16384;  // rows 128..255
    const float* Pupd2  = g_wp + 4 * 128 * 128;

    // ---- load X (tf32-rounded) -> buf0, zero pad rows ----
    for (int i = tid; i < NNODE * H / 4; i += NTHREADS) {
        int row = i >> 5, c4 = (i & 31) << 2;
        float4 v = *reinterpret_cast<const float4*>(xb + row * H + c4);
        float* d = buf0 + row * LDA + c4;
        d[0] = tfF(v.x); d[1] = tfF(v.y); d[2] = tfF(v.z); d[3] = tfF(v.w);
    }
    for (int i = tid; i < (MPAD - NNODE) * H; i += NTHREADS)
        buf0[(NNODE + (i >> 7)) * LDA + (i & 127)] = 0.f;

    float accZ[2][4][4], accXU[2][4][4];
    zero_acc(accZ); zero_acc(accXU);

    // ---- fused pass: Z = X@Wmsg1, XU = X@Wupd1a (A read once) ----
    run_gemm_p<4, true>(buf0 + mw * 32 * LDA, Pmsg1, Pupd1a, sW0, sW1,
                        accZ, accXU, 4, tid, g, t, nw, mtc);
    // epilogue: Z (raw fp32) -> buf1
#pragma unroll
    for (int m = 0; m < 2; ++m) if (m < mtc)
#pragma unroll
        for (int nt = 0; nt < 4; ++nt) {
            int r0 = mw * 32 + m * 16 + g, c0 = nw * 32 + nt * 8 + 2 * t;
            float* p = buf1 + r0 * LDA + c0;
            p[0] = accZ[m][nt][0];       p[1] = accZ[m][nt][1];
            p[8 * LDA] = accZ[m][nt][2]; p[8 * LDA + 1] = accZ[m][nt][3];
        }
    __syncthreads();

    // ---- gather: S[v] = sum_d relu(Z[nbr_d(v)] + c_d) -> buf0 (over X) ----
    {
        int k = tid & 127;
        float wl  = w_msg1[H * H + k];        // (H+1)-th row, unrounded
        float b1v = b_msg1[k];
        float c0v = b1v;
        float c1v = b1v + wl * (1.f / 3.f);
        float c2v = b1v + wl * (2.f / 3.f);
        float c3v = b1v + wl;
        for (int v = (tid >> 7); v < NNODE; v += NTHREADS / 128) {
            int r = v / 10, cc = v - r * 10;
            float s = 0.f;
            if (r < 9)  s += fmaxf(buf1[(v + 10) * LDA + k] + c0v, 0.f);
            if (r > 0)  s += fmaxf(buf1[(v - 10) * LDA + k] + c1v, 0.f);
            if (cc < 9) s += fmaxf(buf1[(v + 1)  * LDA + k] + c2v, 0.f);
            if (cc > 0) s += fmaxf(buf1[(v - 1)  * LDA + k] + c3v, 0.f);
            buf0[v * LDA + k] = tfF(s);
        }
        // pad rows of buf0 already zero from X load
    }

    // ---- GEMM2: AGG = S @ Wmsg2 + indeg*b2 -> buf1 (tf32) ----
    zero_acc(accZ);
    run_gemm_p<8, false>(buf0 + mw * 32 * LDA, Pmsg2, Pmsg2, sW0, sW1,
                         accZ, accZ, 2, tid, g, t, nw, mtc);
#pragma unroll
    for (int m = 0; m < 2; ++m) if (m < mtc)
#pragma unroll
        for (int nt = 0; nt < 4; ++nt) {
            int r0 = mw * 32 + m * 16 + g, c0 = nw * 32 + nt * 8 + 2 * t;
            float id0 = indegf(r0), id1 = indegf(r0 + 8);
            float bb0 = b_msg2[c0], bb1 = b_msg2[c0 + 1];
            float* p = buf1 + r0 * LDA + c0;
            p[0] = tfF(accZ[m][nt][0] + id0 * bb0);
            p[1] = tfF(accZ[m][nt][1] + id0 * bb1);
            p[8 * LDA]     = tfF(accZ[m][nt][2] + id1 * bb0);
            p[8 * LDA + 1] = tfF(accZ[m][nt][3] + id1 * bb1);
        }

    // ---- GEMM3b: accXU += AGG @ Wupd1b; U1 = relu(accXU + bu1) -> buf0 (tf32) ----
    run_gemm_p<8, false>(buf1 + mw * 32 * LDA, Pupd1b, Pupd1b, sW0, sW1,
                         accXU, accXU, 2, tid, g, t, nw, mtc);
#pragma unroll
    for (int m = 0; m < 2; ++m) if (m < mtc)
#pragma unroll
        for (int nt = 0; nt < 4; ++nt) {
            int r0 = mw * 32 + m * 16 + g, c0 = nw * 32 + nt * 8 + 2 * t;
            float bb0 = b_upd1[c0], bb1 = b_upd1[c0 + 1];
            float* p = buf0 + r0 * LDA + c0;
            p[0] = tfF(fmaxf(accXU[m][nt][0] + bb0, 0.f));
            p[1] = tfF(fmaxf(accXU[m][nt][1] + bb1, 0.f));
            p[8 * LDA]     = tfF(fmaxf(accXU[m][nt][2] + bb0, 0.f));
            p[8 * LDA + 1] = tfF(fmaxf(accXU[m][nt][3] + bb1, 0.f));
        }

    // ---- GEMM4: U2 = U1 @ Wupd2 + bu2 -> buf1 (fp32) ----
    zero_acc(accZ);
    run_gemm_p<8, false>(buf0 + mw * 32 * LDA, Pupd2, Pupd2, sW0, sW1,
                         accZ, accZ, 2, tid, g, t, nw, mtc);
#pragma unroll
    for (int m = 0; m < 2; ++m) if (m < mtc)
#pragma unroll
        for (int nt = 0; nt < 4; ++nt) {
            int r0 = mw * 32 + m * 16 + g, c0 = nw * 32 + nt * 8 + 2 * t;
            float bb0 = b_upd2[c0], bb1 = b_upd2[c0 + 1];
            float* p = buf1 + r0 * LDA + c0;
            p[0] = accZ[m][nt][0] + bb0;
            p[1] = accZ[m][nt][1] + bb1;
            p[8 * LDA]     = accZ[m][nt][2] + bb0;
            p[8 * LDA + 1] = accZ[m][nt][3] + bb1;
        }
    __syncthreads();

    // ---- residual (unrounded x) + LayerNorm + store ----
    {
        float* ob = out + (size_t)b * NNODE * H;
        int k4 = lane * 4;
        float g0 = gamma[k4], g1 = gamma[k4 + 1], g2 = gamma[k4 + 2], g3 = gamma[k4 + 3];
        float e0 = beta[k4],  e1 = beta[k4 + 1],  e2 = beta[k4 + 2],  e3 = beta[k4 + 3];
        for (int v = warp; v < NNODE; v += NTHREADS / 32) {
            float4 xv = *reinterpret_cast<const float4*>(xb + v * H + k4);
            const float* hp = buf1 + v * LDA + k4;
            float h0 = hp[0] + xv.x, h1 = hp[1] + xv.y;
            float h2 = hp[2] + xv.z, h3 = hp[3] + xv.w;
            float s = h0 + h1 + h2 + h3;
            float q = h0 * h0 + h1 * h1 + h2 * h2 + h3 * h3;
#pragma unroll
            for (int off = 16; off; off >>= 1) {
                s += __shfl_xor_sync(0xFFFFFFFFu, s, off);
                q += __shfl_xor_sync(0xFFFFFFFFu, q, off);
            }
            float mu  = s * (1.f / 128.f);
            float var = q * (1.f / 128.f) - mu * mu;
            float rs  = rsqrtf(var + 1e-5f);
            float4 o;
            o.x = (h0 - mu) * rs * g0 + e0;
            o.y = (h1 - mu) * rs * g1 + e1;
            o.z = (h2 - mu) * rs * g2 + e2;
            o.w = (h3 - mu) * rs * g3 + e3;
            *reinterpret_cast<float4*>(ob + v * H + k4) = o;
        }
    }
}

extern "C" void kernel_launch(void* const* d_in, const int* in_sizes, int n_in,
                              void* d_out, int out_size) {
    const float* x      = (const float*)d_in[0];
    const float* w_msg1 = (const float*)d_in[4];
    const float* b_msg1 = (const float*)d_in[5];
    const float* w_msg2 = (const float*)d_in[6];
    const float* b_msg2 = (const float*)d_in[7];
    const float* w_upd1 = (const float*)d_in[8];
    const float* b_upd1 = (const float*)d_in[9];
    const float* w_upd2 = (const float*)d_in[10];
    const float* b_upd2 = (const float*)d_in[11];
    const float* gamma  = (const float*)d_in[12];
    const float* beta   = (const float*)d_in[13];
    float* out = (float*)d_out;

    int batches = in_sizes[0] / (NNODE * H);

    prep_kernel<<<320, 256>>>(w_msg1, w_msg2, w_upd1, w_upd2);

    cudaFuncSetAttribute(mpnn_kernel, cudaFuncAttributeMaxDynamicSharedMemorySize, SMEM_BYTES);
    mpnn_kernel<<<batches, NTHREADS, SMEM_BYTES>>>(x, w_msg1, b_msg1, b_msg2,
                                                   b_upd1, b_upd2, gamma, beta, out);
}

// round 17
// speedup vs baseline: 1.0024x; 1.0010x over previous
#include <cuda_runtime.h>

#define NNODE 100
#define H     128
#define MPAD  112
#define LDA   132
#define NBUF  (MPAD*LDA)
#define WCH   8192                 // floats per staged weight chunk buffer
#define SMEM_FLOATS (2*NBUF + 2*WCH)
#define SMEM_BYTES  (SMEM_FLOATS*4)
#define NTHREADS 512

// Fragment-packed tf32 weights: msg1[128] | msg2[128] | upd1[256] | upd2[128] rows.
// Layout per matrix: word[(s*8 + nw*2 + h)*128 + g*16 + t*4 + nt] = W[s*8 + h*4 + t][nw*32 + nt*8 + g]
__device__ float g_wp[640 * H];

__device__ __forceinline__ unsigned f2tf(float f) {
    unsigned u; asm("cvt.rna.tf32.f32 %0, %1;" : "=r"(u) : "f"(f)); return u;
}
__device__ __forceinline__ float tfF(float f) { return __uint_as_float(f2tf(f)); }

__global__ void __launch_bounds__(256) prep_kernel(const float* __restrict__ w_msg1,
                                                   const float* __restrict__ w_msg2,
                                                   const float* __restrict__ w_upd1,
                                                   const float* __restrict__ w_upd2) {
    int i = blockIdx.x * 256 + threadIdx.x;   // 0..81919
    int n = i & 127, r = i >> 7;
    const float* src; int k, base;
    if      (r < 128) { src = w_msg1; k = r;       base = 0; }
    else if (r < 256) { src = w_msg2; k = r - 128; base = 128 * 128; }
    else if (r < 512) { src = w_upd1; k = r - 256; base = 2 * 128 * 128; }
    else              { src = w_upd2; k = r - 512; base = 4 * 128 * 128; }
    float v = src[k * H + n];
    int s = k >> 3, ris = k & 7, h = ris >> 2, t = ris & 3;
    int nw = n >> 5, g = n & 7, nt = (n >> 3) & 3;
    g_wp[base + (s * 8 + nw * 2 + h) * 128 + g * 16 + t * 4 + nt] = tfF(v);
}

__device__ __forceinline__ void mma8(float& d0, float& d1, float& d2, float& d3,
                                     unsigned a0, unsigned a1, unsigned a2, unsigned a3,
                                     unsigned b0, unsigned b1) {
    asm volatile(
        "mma.sync.aligned.m16n8k8.row.col.f32.tf32.tf32.f32 "
        "{%0,%1,%2,%3}, {%4,%5,%6,%7}, {%8,%9}, {%0,%1,%2,%3};"
        : "+f"(d0), "+f"(d1), "+f"(d2), "+f"(d3)
        : "r"(a0), "r"(a1), "r"(a2), "r"(a3), "r"(b0), "r"(b1));
}

__device__ __forceinline__ void cp16(float* dst, const float* src) {
    unsigned d = (unsigned)__cvta_generic_to_shared(dst);
    asm volatile("cp.async.cg.shared.global [%0], [%1], 16;" :: "r"(d), "l"(src));
}
#define CP_COMMIT() asm volatile("cp.async.commit_group;")
#define CP_WAIT0()  asm volatile("cp.async.wait_group 0;")

// Stage one chunk. DUAL: two 4096-word regions (msg1-slab + upd1a-slab). Single: 8192 contiguous.
template<bool DUAL>
__device__ __forceinline__ void stage_chunk(float* sW, const float* __restrict__ g1,
                                            const float* __restrict__ g2, int c, int tid) {
    if (DUAL) {
#pragma unroll
        for (int it = 0; it < 2; ++it) {
            int w4 = (tid + it * NTHREADS) * 4;
            cp16(sW + w4, g1 + c * 4096 + w4);
        }
#pragma unroll
        for (int it = 0; it < 2; ++it) {
            int w4 = (tid + it * NTHREADS) * 4;
            cp16(sW + 4096 + w4, g2 + c * 4096 + w4);
        }
    } else {
#pragma unroll
        for (int it = 0; it < 4; ++it) {
            int w4 = (tid + it * NTHREADS) * 4;
            cp16(sW + w4, g1 + c * 8192 + w4);
        }
    }
}

// One chunk of KT_ k-slabs. sWl = chunk base + nw*256 + g*16 + t*4 (lane-adjusted).
template<int KT_, bool DUAL>
__device__ __forceinline__ void gemm_chunk_p(const float* __restrict__ sA,
                                             const float* __restrict__ sWl,
                                             float accA[2][4][4], float accB[2][4][4],
                                             int g, int t, int mtc) {
#pragma unroll
    for (int kt = 0; kt < KT_; ++kt) {
        unsigned a0[2], a1[2], a2[2], a3[2];
#pragma unroll
        for (int m = 0; m < 2; ++m) if (m < mtc) {
            const float* ap = sA + (m * 16 + g) * LDA + kt * 8 + t;
            a0[m] = __float_as_uint(ap[0]);
            a1[m] = __float_as_uint(ap[8 * LDA]);
            a2[m] = __float_as_uint(ap[4]);
            a3[m] = __float_as_uint(ap[8 * LDA + 4]);
        }
        {
            float4 b0 = *reinterpret_cast<const float4*>(sWl + kt * 1024);
            float4 b1 = *reinterpret_cast<const float4*>(sWl + kt * 1024 + 128);
            const float* b0p = &b0.x; const float* b1p = &b1.x;
#pragma unroll
            for (int m = 0; m < 2; ++m) if (m < mtc)
#pragma unroll
                for (int nt = 0; nt < 4; ++nt)
                    mma8(accA[m][nt][0], accA[m][nt][1], accA[m][nt][2], accA[m][nt][3],
                         a0[m], a1[m], a2[m], a3[m],
                         __float_as_uint(b0p[nt]), __float_as_uint(b1p[nt]));
        }
        if (DUAL) {
            float4 b0 = *reinterpret_cast<const float4*>(sWl + 4096 + kt * 1024);
            float4 b1 = *reinterpret_cast<const float4*>(sWl + 4096 + kt * 1024 + 128);
            const float* b0p = &b0.x; const float* b1p = &b1.x;
#pragma unroll
            for (int m = 0; m < 2; ++m) if (m < mtc)
#pragma unroll
                for (int nt = 0; nt < 4; ++nt)
                    mma8(accB[m][nt][0], accB[m][nt][1], accB[m][nt][2], accB[m][nt][3],
                         a0[m], a1[m], a2[m], a3[m],
                         __float_as_uint(b0p[nt]), __float_as_uint(b1p[nt]));
        }
    }
}

template<int KT_, bool DUAL>
__device__ __forceinline__ void run_gemm_p(const float* sAwarp,
                                           const float* __restrict__ gW1,
                                           const float* __restrict__ gW2,
                                           float* sW0, float* sW1,
                                           float accA[2][4][4], float accB[2][4][4],
                                           int chunks, int tid, int g, int t, int nw, int mtc) {
    __syncthreads();                       // A ready; weight buffers free
    stage_chunk<DUAL>(sW0, gW1, gW2, 0, tid);
    CP_COMMIT();
    for (int c = 0; c < chunks; ++c) {
        CP_WAIT0();
        __syncthreads();
        float* cur = (c & 1) ? sW1 : sW0;
        if (c + 1 < chunks) {
            float* nxt = (c & 1) ? sW0 : sW1;
            stage_chunk<DUAL>(nxt, gW1, gW2, c + 1, tid);
            CP_COMMIT();
        }
        gemm_chunk_p<KT_, DUAL>(sAwarp + c * (KT_ * 8),
                                cur + nw * 256 + g * 16 + t * 4,
                                accA, accB, g, t, mtc);
    }
}

__device__ __forceinline__ float indegf(int row) {
    int r = row / 10, c = row - r * 10;
    return (float)((r > 0) + (r < 9) + (c > 0) + (c < 9));
}

__device__ __forceinline__ void zero_acc(float acc[2][4][4]) {
#pragma unroll
    for (int m = 0; m < 2; ++m)
#pragma unroll
        for (int nt = 0; nt < 4; ++nt)
#pragma unroll
            for (int j = 0; j < 4; ++j) acc[m][nt][j] = 0.f;
}

extern "C" __global__ void __launch_bounds__(NTHREADS, 1)
mpnn_kernel(const float* __restrict__ x,
            const float* __restrict__ w_msg1, const float* __restrict__ b_msg1,
            const float* __restrict__ b_msg2,
            const float* __restrict__ b_upd1,
            const float* __restrict__ b_upd2,
            const float* __restrict__ gamma,  const float* __restrict__ beta,
            float* __restrict__ out) {
    extern __shared__ float sm[];
    float* buf0 = sm;                  // X -> S -> U1
    float* buf1 = sm + NBUF;           // Z -> AGG -> h
    float* sW0  = sm + 2 * NBUF;
    float* sW1  = sW0 + WCH;

    const int tid  = threadIdx.x;
    const int warp = tid >> 5, lane = tid & 31;
    const int g = lane >> 2, t = lane & 3;
    const int mw = warp >> 2, nw = warp & 3;     // 4 M-warps x 4 N-warps
    const int mtc = (mw == 3) ? 1 : 2;
    const int b = blockIdx.x;
    const float* xb = x + (size_t)b * NNODE * H;

    const float* Pmsg1  = g_wp;
    const float* Pmsg2  = g_wp + 128 * 128;
    const float* Pupd1a = g_wp + 2 * 128 * 128;          // rows 0..127
    const float* Pupd1b = g_wp + 2 * 128 * 128 + 16384;  // rows 128..255
    const float* Pupd2  = g_wp + 4 * 128 * 128;

    // ---- load X (tf32-rounded) -> buf0, zero pad rows ----
    for (int i = tid; i < NNODE * H / 4; i += NTHREADS) {
        int row = i >> 5, c4 = (i & 31) << 2;
        float4 v = *reinterpret_cast<const float4*>(xb + row * H + c4);
        float* d = buf0 + row * LDA + c4;
        d[0] = tfF(v.x); d[1] = tfF(v.y); d[2] = tfF(v.z); d[3] = tfF(v.w);
    }
    for (int i = tid; i < (MPAD - NNODE) * H; i += NTHREADS)
        buf0[(NNODE + (i >> 7)) * LDA + (i & 127)] = 0.f;

    float accZ[2][4][4], accXU[2][4][4];
    zero_acc(accZ); zero_acc(accXU);

    // ---- fused pass: Z = X@Wmsg1, XU = X@Wupd1a (A read once) ----
    run_gemm_p<4, true>(buf0 + mw * 32 * LDA, Pmsg1, Pupd1a, sW0, sW1,
                        accZ, accXU, 4, tid, g, t, nw, mtc);
    // epilogue: Z (raw fp32) -> buf1
#pragma unroll
    for (int m = 0; m < 2; ++m) if (m < mtc)
#pragma unroll
        for (int nt = 0; nt < 4; ++nt) {
            int r0 = mw * 32 + m * 16 + g, c0 = nw * 32 + nt * 8 + 2 * t;
            float* p = buf1 + r0 * LDA + c0;
            p[0] = accZ[m][nt][0];       p[1] = accZ[m][nt][1];
            p[8 * LDA] = accZ[m][nt][2]; p[8 * LDA + 1] = accZ[m][nt][3];
        }
    __syncthreads();

    // ---- gather: S[v] = sum_d relu(Z[nbr_d(v)] + c_d) -> buf0 (over X) ----
    {
        int k = tid & 127;
        float wl  = w_msg1[H * H + k];        // (H+1)-th row, unrounded
        float b1v = b_msg1[k];
        float c0v = b1v;
        float c1v = b1v + wl * (1.f / 3.f);
        float c2v = b1v + wl * (2.f / 3.f);
        float c3v = b1v + wl;
        for (int v = (tid >> 7); v < NNODE; v += NTHREADS / 128) {
            int r = v / 10, cc = v - r * 10;
            float s = 0.f;
            if (r < 9)  s += fmaxf(buf1[(v + 10) * LDA + k] + c0v, 0.f);
            if (r > 0)  s += fmaxf(buf1[(v - 10) * LDA + k] + c1v, 0.f);
            if (cc < 9) s += fmaxf(buf1[(v + 1)  * LDA + k] + c2v, 0.f);
            if (cc > 0) s += fmaxf(buf1[(v - 1)  * LDA + k] + c3v, 0.f);
            buf0[v * LDA + k] = tfF(s);
        }
        // pad rows of buf0 already zero from X load
    }

    // ---- GEMM2: AGG = S @ Wmsg2 + indeg*b2 -> buf1 (tf32) ----
    zero_acc(accZ);
    run_gemm_p<8, false>(buf0 + mw * 32 * LDA, Pmsg2, Pmsg2, sW0, sW1,
                         accZ, accZ, 2, tid, g, t, nw, mtc);
#pragma unroll
    for (int m = 0; m < 2; ++m) if (m < mtc)
#pragma unroll
        for (int nt = 0; nt < 4; ++nt) {
            int r0 = mw * 32 + m * 16 + g, c0 = nw * 32 + nt * 8 + 2 * t;
            float id0 = indegf(r0), id1 = indegf(r0 + 8);
            float bb0 = b_msg2[c0], bb1 = b_msg2[c0 + 1];
            float* p = buf1 + r0 * LDA + c0;
            p[0] = tfF(accZ[m][nt][0] + id0 * bb0);
            p[1] = tfF(accZ[m][nt][1] + id0 * bb1);
            p[8 * LDA]     = tfF(accZ[m][nt][2] + id1 * bb0);
            p[8 * LDA + 1] = tfF(accZ[m][nt][3] + id1 * bb1);
        }

    // ---- GEMM3b: accXU += AGG @ Wupd1b; U1 = relu(accXU + bu1) -> buf0 (tf32) ----
    run_gemm_p<8, false>(buf1 + mw * 32 * LDA, Pupd1b, Pupd1b, sW0, sW1,
                         accXU, accXU, 2, tid, g, t, nw, mtc);
#pragma unroll
    for (int m = 0; m < 2; ++m) if (m < mtc)
#pragma unroll
        for (int nt = 0; nt < 4; ++nt) {
            int r0 = mw * 32 + m * 16 + g, c0 = nw * 32 + nt * 8 + 2 * t;
            float bb0 = b_upd1[c0], bb1 = b_upd1[c0 + 1];
            float* p = buf0 + r0 * LDA + c0;
            p[0] = tfF(fmaxf(accXU[m][nt][0] + bb0, 0.f));
            p[1] = tfF(fmaxf(accXU[m][nt][1] + bb1, 0.f));
            p[8 * LDA]     = tfF(fmaxf(accXU[m][nt][2] + bb0, 0.f));
            p[8 * LDA + 1] = tfF(fmaxf(accXU[m][nt][3] + bb1, 0.f));
        }

    // ---- GEMM4: U2 = U1 @ Wupd2 + bu2 -> buf1 (fp32) ----
    zero_acc(accZ);
    run_gemm_p<8, false>(buf0 + mw * 32 * LDA, Pupd2, Pupd2, sW0, sW1,
                         accZ, accZ, 2, tid, g, t, nw, mtc);
#pragma unroll
    for (int m = 0; m < 2; ++m) if (m < mtc)
#pragma unroll
        for (int nt = 0; nt < 4; ++nt) {
            int r0 = mw * 32 + m * 16 + g, c0 = nw * 32 + nt * 8 + 2 * t;
            float bb0 = b_upd2[c0], bb1 = b_upd2[c0 + 1];
            float* p = buf1 + r0 * LDA + c0;
            p[0] = accZ[m][nt][0] + bb0;
            p[1] = accZ[m][nt][1] + bb1;
            p[8 * LDA]     = accZ[m][nt][2] + bb0;
            p[8 * LDA + 1] = accZ[m][nt][3] + bb1;
        }
    __syncthreads();

    // ---- residual (unrounded x) + LayerNorm + store ----
    {
        float* ob = out + (size_t)b * NNODE * H;
        int k4 = lane * 4;
        float g0 = gamma[k4], g1 = gamma[k4 + 1], g2 = gamma[k4 + 2], g3 = gamma[k4 + 3];
        float e0 = beta[k4],  e1 = beta[k4 + 1],  e2 = beta[k4 + 2],  e3 = beta[k4 + 3];
        for (int v = warp; v < NNODE; v += NTHREADS / 32) {
            float4 xv = *reinterpret_cast<const float4*>(xb + v * H + k4);
            const float* hp = buf1 + v * LDA + k4;
            float h0 = hp[0] + xv.x, h1 = hp[1] + xv.y;
            float h2 = hp[2] + xv.z, h3 = hp[3] + xv.w;
            float s = h0 + h1 + h2 + h3;
            float q = h0 * h0 + h1 * h1 + h2 * h2 + h3 * h3;
#pragma unroll
            for (int off = 16; off; off >>= 1) {
                s += __shfl_xor_sync(0xFFFFFFFFu, s, off);
                q += __shfl_xor_sync(0xFFFFFFFFu, q, off);
            }
            float mu  = s * (1.f / 128.f);
            float var = q * (1.f / 128.f) - mu * mu;
            float rs  = rsqrtf(var + 1e-5f);
            float4 o;
            o.x = (h0 - mu) * rs * g0 + e0;
            o.y = (h1 - mu) * rs * g1 + e1;
            o.z = (h2 - mu) * rs * g2 + e2;
            o.w = (h3 - mu) * rs * g3 + e3;
            *reinterpret_cast<float4*>(ob + v * H + k4) = o;
        }
    }
}

extern "C" void kernel_launch(void* const* d_in, const int* in_sizes, int n_in,
                              void* d_out, int out_size) {
    const float* x      = (const float*)d_in[0];
    const float* w_msg1 = (const float*)d_in[4];
    const float* b_msg1 = (const float*)d_in[5];
    const float* w_msg2 = (const float*)d_in[6];
    const float* b_msg2 = (const float*)d_in[7];
    const float* w_upd1 = (const float*)d_in[8];
    const float* b_upd1 = (const float*)d_in[9];
    const float* w_upd2 = (const float*)d_in[10];
    const float* b_upd2 = (const float*)d_in[11];
    const float* gamma  = (const float*)d_in[12];
    const float* beta   = (const float*)d_in[13];
    float* out = (float*)d_out;

    int batches = in_sizes[0] / (NNODE * H);

    prep_kernel<<<320, 256>>>(w_msg1, w_msg2, w_upd1, w_upd2);

    cudaFuncSetAttribute(mpnn_kernel, cudaFuncAttributeMaxDynamicSharedMemorySize, SMEM_BYTES);
    mpnn_kernel<<<batches, NTHREADS, SMEM_BYTES>>>(x, w_msg1, b_msg1, b_msg2,
                                                   b_upd1, b_upd2, gamma, beta, out);
}